// round 9
// baseline (speedup 1.0000x reference)
#include <cuda_runtime.h>

#define HID  128
#define NH   8
#define NSEQ 4096
#define BP   4
#define SROW 4097   // h has 4097 rows per batch; last row is hg
#define FULL 0xffffffffu

__device__ float g_u[BP*NH*HID];
__device__ float g_w[BP*NH*HID];     // UNNORMALIZED sum of e_n * hn
__device__ float g_sum[BP*NH];       // sum of e_n
__device__ float g_a[BP*NSEQ];
__device__ float g_bv[BP*NSEQ];

__device__ __forceinline__ float wsum(float v) {
    #pragma unroll
    for (int o = 16; o; o >>= 1) v += __shfl_xor_sync(FULL, v, o);
    return v;
}

// ---------------- A: q = hg@W_q ; u_h = W_k_head@q_h ; zero accumulators (all batches) ----------------
__global__ void kA(const float* __restrict__ h, const float* __restrict__ Wq,
                   const float* __restrict__ Wkv) {
    int b = blockIdx.x, tid = threadIdx.x;           // 512 threads
    g_w[b*NH*HID + tid]       = 0.f;
    g_w[b*NH*HID + 512 + tid] = 0.f;
    if (tid < NH) g_sum[b*NH + tid] = 0.f;

    int t = tid & 127, k = tid >> 7;
    __shared__ float hg[HID], qp[4][HID], qs[HID];
    if (tid < HID) hg[tid] = h[((size_t)b*SROW + NSEQ)*HID + tid];
    __syncthreads();
    float q = 0.f;
    #pragma unroll
    for (int d = k*32; d < k*32 + 32; d++) q += hg[d]*Wq[d*HID + t];
    qp[k][t] = q;
    __syncthreads();
    if (tid < HID) qs[tid] = qp[0][tid] + qp[1][tid] + qp[2][tid] + qp[3][tid];
    __syncthreads();
    #pragma unroll
    for (int it = 0; it < 2; it++) {
        int idx = tid + it*512;
        int hh = idx >> 7, tt = idx & 127;
        float u = 0.f;
        #pragma unroll
        for (int d = 0; d < 16; d++) u += Wkv[tt*256 + hh*16 + d]*qs[hh*16 + d];
        g_u[(b*NH + hh)*HID + tt] = u;
    }
}

// ==== kBC (per batch): scores -> exp -> accumulate w, esum ====
// grid NSEQ/32 x 256 threads; 8 warps x 4 rows; transpose-reduce, 1 exp/thread.
__global__ void kBC(const float* __restrict__ h, int b) {
    int tid = threadIdx.x;
    int warp = tid >> 5, lane = tid & 31;
    __shared__ float4 us4[NH][32];
    ((float4*)us4)[tid] = ((const float4*)&g_u[b*NH*HID])[tid];
    __syncthreads();

    int row0 = blockIdx.x*32 + warp*4;
    const float* base = &h[((size_t)b*SROW + row0)*HID];
    float4 r[4];
    #pragma unroll
    for (int i = 0; i < 4; i++)
        r[i] = *(const float4*)&base[(size_t)i*HID + lane*4];

    float p[32];
    #pragma unroll
    for (int hh = 0; hh < NH; hh++) {
        float4 u4 = us4[hh][lane];
        #pragma unroll
        for (int i = 0; i < 4; i++)
            p[hh*4 + i] = r[i].x*u4.x + r[i].y*u4.y + r[i].z*u4.z + r[i].w*u4.w;
    }
    #pragma unroll
    for (int off = 16; off; off >>= 1) {
        bool up = (lane & off) != 0;
        #pragma unroll
        for (int k = 0; k < off; k++) {
            float a_ = p[k], b_ = p[k + off];
            float send = up ? a_ : b_;
            float keep = up ? b_ : a_;
            p[k] = keep + __shfl_xor_sync(FULL, send, off);
        }
    }
    float ev = __expf(0.25f*p[0]);          // lane l owns dot l (hh = l>>2, i = l&3)

    float4 acc[NH]; float eh[NH];
    #pragma unroll
    for (int hh = 0; hh < NH; hh++) {
        acc[hh] = make_float4(0.f,0.f,0.f,0.f); eh[hh] = 0.f;
        #pragma unroll
        for (int i = 0; i < 4; i++) {
            float e = __shfl_sync(FULL, ev, hh*4 + i);
            eh[hh] += e;
            acc[hh].x += e*r[i].x; acc[hh].y += e*r[i].y;
            acc[hh].z += e*r[i].z; acc[hh].w += e*r[i].w;
        }
    }
    __shared__ float4 smw[8][NH][32];       // 32KB
    __shared__ float  ses[8][NH];
    #pragma unroll
    for (int hh = 0; hh < NH; hh++) smw[warp][hh][lane] = acc[hh];
    if (lane == 0) {
        #pragma unroll
        for (int hh = 0; hh < NH; hh++) ses[warp][hh] = eh[hh];
    }
    __syncthreads();
    int hh2 = tid >> 5;
    float4 rs = smw[0][hh2][lane];
    #pragma unroll
    for (int s = 1; s < 8; s++) {
        float4 v = smw[s][hh2][lane];
        rs.x += v.x; rs.y += v.y; rs.z += v.z; rs.w += v.w;
    }
    float* dst = &g_w[(b*NH + hh2)*HID + lane*4];
    atomicAdd(dst+0, rs.x); atomicAdd(dst+1, rs.y);
    atomicAdd(dst+2, rs.z); atomicAdd(dst+3, rs.w);
    if (tid < NH) {
        float s = 0.f;
        #pragma unroll
        for (int w2 = 0; w2 < 8; w2++) s += ses[w2][tid];
        atomicAdd(&g_sum[b*NH + tid], s);
    }
}

// ==== kDE (per batch): normalize w; y = w@W_v; mh = y@W_mhc; y2 = mh.hn; a/bv ====
// grid NSEQ/128 x 256 threads (8 warps x 16 rows).
__global__ void kDE(const float* __restrict__ h, const float* __restrict__ Wkv,
                    const float* __restrict__ Wmhc, const float* __restrict__ Wlin, int b) {
    int tid = threadIdx.x;
    int t = tid & 127, k = tid >> 7;                 // k: 0..1
    __shared__ float ws[NH*HID], ys[HID], ms[HID], part[2][HID];
    __shared__ float ssum[NH], w01[2];
    if (tid < NH) ssum[tid] = g_sum[b*NH + tid];
    if (tid < 2)  w01[tid]  = Wlin[tid];
    __syncthreads();
    #pragma unroll
    for (int it = 0; it < 4; it++) {
        int i = tid + it*256;
        ws[i] = g_w[b*NH*HID + i] / ssum[i >> 7];
    }
    __syncthreads();
    int hh = t >> 4;
    float y = 0.f;
    #pragma unroll
    for (int jj = k*64; jj < k*64 + 64; jj++) y += ws[hh*HID + jj]*Wkv[jj*256 + HID + t];
    part[k][t] = y;
    __syncthreads();
    if (tid < HID) ys[tid] = part[0][tid] + part[1][tid];
    __syncthreads();
    float m = 0.f;
    #pragma unroll
    for (int c = k*64; c < k*64 + 64; c++) m += ys[c]*Wmhc[c*HID + t];
    part[k][t] = m;
    __syncthreads();
    if (tid < HID) ms[tid] = part[0][tid] + part[1][tid];
    __syncthreads();

    int warp = tid >> 5, lane = tid & 31;
    float4 m4 = ((float4*)ms)[lane];
    int row0 = blockIdx.x*128 + warp*16;
    const float* base = &h[((size_t)b*SROW + row0)*HID];
    float out = 0.f;
    #pragma unroll
    for (int i = 0; i < 16; i++) {
        float4 r = *(const float4*)&base[(size_t)i*HID + lane*4];
        float d = r.x*m4.x + r.y*m4.y + r.z*m4.z + r.w*m4.w;
        d = wsum(d);
        if (lane == i) out = d;
    }
    if (lane < 16) {
        g_a [b*NSEQ + row0 + lane] = out*w01[0];
        g_bv[b*NSEQ + row0 + lane] = out*w01[1];
    }
}

// ==== kF (per batch): out[b, i*N + j] = a[b,j] + bv[b,i]  (67MB stream) ====
#define ROWS_F 8
__global__ void kF(float* __restrict__ out, int b) {
    int t = threadIdx.x;                                     // 1024 threads
    int i0 = blockIdx.x*ROWS_F;
    float4 a4 = ((const float4*)&g_a[b*NSEQ])[t];
    const float* bv = &g_bv[b*NSEQ];
    float4* ob = (float4*)&out[((size_t)b*NSEQ + i0)*NSEQ];
    #pragma unroll
    for (int r = 0; r < ROWS_F; r++) {
        float bi = bv[i0 + r];
        float4 o4 = make_float4(a4.x+bi, a4.y+bi, a4.z+bi, a4.w+bi);
        __stwt(&ob[(size_t)r*(NSEQ/4) + t], o4);
    }
}

// ---- streams/events created once at module load (host objects only) ----
static cudaStream_t g_sA, g_sB;
static cudaEvent_t  g_evRoot, g_evChain[BP], g_evDone;
namespace {
struct StreamInit {
    StreamInit() {
        cudaStreamCreateWithFlags(&g_sA, cudaStreamNonBlocking);
        cudaStreamCreateWithFlags(&g_sB, cudaStreamNonBlocking);
        cudaEventCreateWithFlags(&g_evRoot, cudaEventDisableTiming);
        for (int i = 0; i < BP; i++)
            cudaEventCreateWithFlags(&g_evChain[i], cudaEventDisableTiming);
        cudaEventCreateWithFlags(&g_evDone, cudaEventDisableTiming);
    }
};
static StreamInit g_streamInit;
}

extern "C" void kernel_launch(void* const* d_in, const int* in_sizes, int n_in,
                              void* d_out, int out_size) {
    const float* h    = (const float*)d_in[0];
    const float* Wq   = (const float*)d_in[1];
    const float* Wkv  = (const float*)d_in[2];
    const float* Wmhc = (const float*)d_in[3];
    const float* Wlin = (const float*)d_in[4];
    float* out = (float*)d_out;

    // staggered 2-stream pipeline: chain(b) serial on sA; kF(b) on sB after chain(b).
    cudaEventRecord(g_evRoot, 0);
    cudaStreamWaitEvent(g_sA, g_evRoot, 0);
    cudaStreamWaitEvent(g_sB, g_evRoot, 0);

    kA<<<BP, 512, 0, g_sA>>>(h, Wq, Wkv);
    for (int b = 0; b < BP; b++) {
        kBC<<<NSEQ/32,  256, 0, g_sA>>>(h, b);
        kDE<<<NSEQ/128, 256, 0, g_sA>>>(h, Wkv, Wmhc, Wlin, b);
        cudaEventRecord(g_evChain[b], g_sA);
        cudaStreamWaitEvent(g_sB, g_evChain[b], 0);
        kF<<<NSEQ/ROWS_F, 1024, 0, g_sB>>>(out, b);
    }
    cudaEventRecord(g_evDone, g_sB);
    cudaStreamWaitEvent(0, g_evDone, 0);
}

// round 10
// speedup vs baseline: 1.2933x; 1.2933x over previous
#include <cuda_runtime.h>

#define HID  128
#define NH   8
#define NSEQ 4096
#define BP   4
#define SROW 4097   // h has 4097 rows per batch; last row is hg
#define FULL 0xffffffffu

__device__ float g_u[BP*NH*HID];
__device__ float g_w[BP*NH*HID];     // UNNORMALIZED sum of e_n * hn
__device__ float g_sum[BP*NH];       // sum of e_n
__device__ float g_a[BP*NSEQ];
__device__ float g_bv[BP*NSEQ];

__device__ __forceinline__ float wsum(float v) {
    #pragma unroll
    for (int o = 16; o; o >>= 1) v += __shfl_xor_sync(FULL, v, o);
    return v;
}

// ---------------- kA: q = hg@W_q ; u_h = W_k_head@q_h ; zero accumulators ----------------
__global__ void kA(const float* __restrict__ h, const float* __restrict__ Wq,
                   const float* __restrict__ Wkv) {
    int b = blockIdx.x, tid = threadIdx.x;           // 512 threads
    g_w[b*NH*HID + tid]       = 0.f;
    g_w[b*NH*HID + 512 + tid] = 0.f;
    if (tid < NH) g_sum[b*NH + tid] = 0.f;

    int t = tid & 127, k = tid >> 7;
    __shared__ float hg[HID], qp[4][HID], qs[HID];
    if (tid < HID) hg[tid] = h[((size_t)b*SROW + NSEQ)*HID + tid];
    __syncthreads();
    float q = 0.f;
    #pragma unroll
    for (int d = k*32; d < k*32 + 32; d++) q += hg[d]*Wq[d*HID + t];
    qp[k][t] = q;
    __syncthreads();
    if (tid < HID) qs[tid] = qp[0][tid] + qp[1][tid] + qp[2][tid] + qp[3][tid];
    __syncthreads();
    #pragma unroll
    for (int it = 0; it < 2; it++) {
        int idx = tid + it*512;
        int hh = idx >> 7, tt = idx & 127;
        float u = 0.f;
        #pragma unroll
        for (int d = 0; d < 16; d++) u += Wkv[tt*256 + hh*16 + d]*qs[hh*16 + d];
        g_u[(b*NH + hh)*HID + tt] = u;
    }
}

// ==== role BC: scores -> exp -> accumulate w, esum  (128 blocks/batch, 256 thr) ====
__device__ void roleBC(const float* __restrict__ h, int b, int blk) {
    int tid = threadIdx.x;
    int warp = tid >> 5, lane = tid & 31;
    __shared__ float4 us4[NH][32];
    ((float4*)us4)[tid] = ((const float4*)&g_u[b*NH*HID])[tid];
    __syncthreads();

    int row0 = blk*32 + warp*4;
    const float* base = &h[((size_t)b*SROW + row0)*HID];
    float4 r[4];
    #pragma unroll
    for (int i = 0; i < 4; i++)
        r[i] = *(const float4*)&base[(size_t)i*HID + lane*4];

    float p[32];
    #pragma unroll
    for (int hh = 0; hh < NH; hh++) {
        float4 u4 = us4[hh][lane];
        #pragma unroll
        for (int i = 0; i < 4; i++)
            p[hh*4 + i] = r[i].x*u4.x + r[i].y*u4.y + r[i].z*u4.z + r[i].w*u4.w;
    }
    #pragma unroll
    for (int off = 16; off; off >>= 1) {
        bool up = (lane & off) != 0;
        #pragma unroll
        for (int k = 0; k < off; k++) {
            float a_ = p[k], b_ = p[k + off];
            float send = up ? a_ : b_;
            float keep = up ? b_ : a_;
            p[k] = keep + __shfl_xor_sync(FULL, send, off);
        }
    }
    float ev = __expf(0.25f*p[0]);          // lane l owns dot l (hh = l>>2, i = l&3)

    float4 acc[NH]; float eh[NH];
    #pragma unroll
    for (int hh = 0; hh < NH; hh++) {
        acc[hh] = make_float4(0.f,0.f,0.f,0.f); eh[hh] = 0.f;
        #pragma unroll
        for (int i = 0; i < 4; i++) {
            float e = __shfl_sync(FULL, ev, hh*4 + i);
            eh[hh] += e;
            acc[hh].x += e*r[i].x; acc[hh].y += e*r[i].y;
            acc[hh].z += e*r[i].z; acc[hh].w += e*r[i].w;
        }
    }
    __shared__ float4 smw[8][NH][32];       // 32KB
    __shared__ float  ses[8][NH];
    #pragma unroll
    for (int hh = 0; hh < NH; hh++) smw[warp][hh][lane] = acc[hh];
    if (lane == 0) {
        #pragma unroll
        for (int hh = 0; hh < NH; hh++) ses[warp][hh] = eh[hh];
    }
    __syncthreads();
    int hh2 = tid >> 5;
    float4 rs = smw[0][hh2][lane];
    #pragma unroll
    for (int s = 1; s < 8; s++) {
        float4 v = smw[s][hh2][lane];
        rs.x += v.x; rs.y += v.y; rs.z += v.z; rs.w += v.w;
    }
    float* dst = &g_w[(b*NH + hh2)*HID + lane*4];
    atomicAdd(dst+0, rs.x); atomicAdd(dst+1, rs.y);
    atomicAdd(dst+2, rs.z); atomicAdd(dst+3, rs.w);
    if (tid < NH) {
        float s = 0.f;
        #pragma unroll
        for (int w2 = 0; w2 < 8; w2++) s += ses[w2][tid];
        atomicAdd(&g_sum[b*NH + tid], s);
    }
}

// ==== role DE: normalize w; y = w@W_v; mh = y@W_mhc; y2 = mh.hn; a/bv  (32 blocks/batch) ====
__device__ void roleDE(const float* __restrict__ h, const float* __restrict__ Wkv,
                       const float* __restrict__ Wmhc, const float* __restrict__ Wlin,
                       int b, int blk) {
    int tid = threadIdx.x;
    int t = tid & 127, k = tid >> 7;                 // k: 0..1
    __shared__ float ws[NH*HID], ys[HID], ms[HID], part[2][HID];
    __shared__ float ssum[NH], w01[2];
    if (tid < NH) ssum[tid] = g_sum[b*NH + tid];
    if (tid < 2)  w01[tid]  = Wlin[tid];
    __syncthreads();
    #pragma unroll
    for (int it = 0; it < 4; it++) {
        int i = tid + it*256;
        ws[i] = g_w[b*NH*HID + i] / ssum[i >> 7];
    }
    __syncthreads();
    int hh = t >> 4;
    float y = 0.f;
    #pragma unroll
    for (int jj = k*64; jj < k*64 + 64; jj++) y += ws[hh*HID + jj]*Wkv[jj*256 + HID + t];
    part[k][t] = y;
    __syncthreads();
    if (tid < HID) ys[tid] = part[0][tid] + part[1][tid];
    __syncthreads();
    float m = 0.f;
    #pragma unroll
    for (int c = k*64; c < k*64 + 64; c++) m += ys[c]*Wmhc[c*HID + t];
    part[k][t] = m;
    __syncthreads();
    if (tid < HID) ms[tid] = part[0][tid] + part[1][tid];
    __syncthreads();

    int warp = tid >> 5, lane = tid & 31;
    float4 m4 = ((float4*)ms)[lane];
    int row0 = blk*128 + warp*16;
    const float* base = &h[((size_t)b*SROW + row0)*HID];
    float out = 0.f;
    #pragma unroll
    for (int i = 0; i < 16; i++) {
        float4 r = *(const float4*)&base[(size_t)i*HID + lane*4];
        float d = r.x*m4.x + r.y*m4.y + r.z*m4.z + r.w*m4.w;
        d = wsum(d);
        if (lane == i) out = d;
    }
    if (lane < 16) {
        g_a [b*NSEQ + row0 + lane] = out*w01[0];
        g_bv[b*NSEQ + row0 + lane] = out*w01[1];
    }
}

// ==== role F: out[b, i*N + j] = a[b,j] + bv[b,i]  (4 rows/block, 1024 blocks/batch, 256 thr) ====
__device__ void roleF(float* __restrict__ out, int b, int blk) {
    int t = threadIdx.x;
    float4 a4[4];
    #pragma unroll
    for (int k = 0; k < 4; k++)
        a4[k] = ((const float4*)&g_a[b*NSEQ])[t + 256*k];
    const float* bv = &g_bv[b*NSEQ];
    int i0 = blk*4;
    float4* ob = (float4*)&out[((size_t)b*NSEQ + i0)*NSEQ];
    #pragma unroll
    for (int r = 0; r < 4; r++) {
        float bi = bv[i0 + r];
        #pragma unroll
        for (int k = 0; k < 4; k++) {
            float4 o4 = make_float4(a4[k].x+bi, a4[k].y+bi, a4[k].z+bi, a4[k].w+bi);
            __stwt(&ob[(size_t)r*(NSEQ/4) + t + 256*k], o4);
        }
    }
}

// ==== fused dispatcher: chain roles first (wave-1 residency), kF blocks after ====
__global__ void __launch_bounds__(256)
kFuse(float* __restrict__ out, const float* __restrict__ h,
      const float* __restrict__ Wkv, const float* __restrict__ Wmhc,
      const float* __restrict__ Wlin,
      int nBC, int bcB0, int nDE, int deB0, int fB) {
    int bx = blockIdx.x;
    if (bx < nBC)            { roleBC(h, bcB0 + bx/128, bx % 128); return; }
    bx -= nBC;
    if (bx < nDE)            { roleDE(h, Wkv, Wmhc, Wlin, deB0 + bx/32, bx % 32); return; }
    bx -= nDE;
    roleF(out, fB + bx/1024, bx % 1024);
}

extern "C" void kernel_launch(void* const* d_in, const int* in_sizes, int n_in,
                              void* d_out, int out_size) {
    const float* h    = (const float*)d_in[0];
    const float* Wq   = (const float*)d_in[1];
    const float* Wkv  = (const float*)d_in[2];
    const float* Wmhc = (const float*)d_in[3];
    const float* Wlin = (const float*)d_in[4];
    float* out = (float*)d_out;

    // single-stream software pipeline; every producer 1+ launches ahead of its consumer
    kA<<<BP, 512>>>(h, Wq, Wkv);
    kFuse<<< 128, 256>>>(out, h, Wkv, Wmhc, Wlin, 128, 0,  0, 0, 0);  // BC(0)
    kFuse<<< 160, 256>>>(out, h, Wkv, Wmhc, Wlin, 128, 1, 32, 0, 0);  // BC(1) | DE(0)
    kFuse<<<1184, 256>>>(out, h, Wkv, Wmhc, Wlin, 128, 2, 32, 1, 0);  // BC(2) | DE(1) | F(0)
    kFuse<<<1184, 256>>>(out, h, Wkv, Wmhc, Wlin, 128, 3, 32, 2, 1);  // BC(3) | DE(2) | F(1)
    kFuse<<<1056, 256>>>(out, h, Wkv, Wmhc, Wlin,   0, 0, 32, 3, 2);  //         DE(3) | F(2)
    kFuse<<<1024, 256>>>(out, h, Wkv, Wmhc, Wlin,   0, 0,  0, 0, 3);  //                 F(3)
}

// round 11
// speedup vs baseline: 1.3005x; 1.0056x over previous
#include <cuda_runtime.h>

#define HID  128
#define NH   8
#define NSEQ 4096
#define BP   4
#define SROW 4097   // h has 4097 rows per batch; last row is hg
#define FULL 0xffffffffu

__device__ float g_u[BP*NH*HID];
__device__ float g_w[BP*NH*HID];     // UNNORMALIZED sum of e_n * hn
__device__ float g_sum[BP*NH];       // sum of e_n
__device__ float g_a[BP*NSEQ];
__device__ float g_bv[BP*NSEQ];

__device__ __forceinline__ float wsum(float v) {
    #pragma unroll
    for (int o = 16; o; o >>= 1) v += __shfl_xor_sync(FULL, v, o);
    return v;
}

// ---------------- kA: q = hg@W_q ; u_h = W_k_head@q_h ; zero accumulators ----------------
__global__ void kA(const float* __restrict__ h, const float* __restrict__ Wq,
                   const float* __restrict__ Wkv) {
    int b = blockIdx.x, tid = threadIdx.x;           // 512 threads
    g_w[b*NH*HID + tid]       = 0.f;
    g_w[b*NH*HID + 512 + tid] = 0.f;
    if (tid < NH) g_sum[b*NH + tid] = 0.f;

    int t = tid & 127, k = tid >> 7;
    __shared__ float hg[HID], qp[4][HID], qs[HID];
    if (tid < HID) hg[tid] = h[((size_t)b*SROW + NSEQ)*HID + tid];
    __syncthreads();
    float q = 0.f;
    #pragma unroll
    for (int d = k*32; d < k*32 + 32; d++) q += hg[d]*Wq[d*HID + t];
    qp[k][t] = q;
    __syncthreads();
    if (tid < HID) qs[tid] = qp[0][tid] + qp[1][tid] + qp[2][tid] + qp[3][tid];
    __syncthreads();
    #pragma unroll
    for (int it = 0; it < 2; it++) {
        int idx = tid + it*512;
        int hh = idx >> 7, tt = idx & 127;
        float u = 0.f;
        #pragma unroll
        for (int d = 0; d < 16; d++) u += Wkv[tt*256 + hh*16 + d]*qs[hh*16 + d];
        g_u[(b*NH + hh)*HID + tt] = u;
    }
}

// ==== role BC: scores -> exp -> accumulate w, esum  (128 blocks/batch, 256 thr) ====
// two-stage warp reduce: smw is [4] deep (16KB) instead of [8] (32KB).
__device__ void roleBC(const float* __restrict__ h, int b, int blk) {
    int tid = threadIdx.x;
    int warp = tid >> 5, lane = tid & 31;
    __shared__ float4 us4[NH][32];                   // 2KB
    ((float4*)us4)[tid] = ((const float4*)&g_u[b*NH*HID])[tid];
    __syncthreads();

    int row0 = blk*32 + warp*4;
    const float* base = &h[((size_t)b*SROW + row0)*HID];
    float4 r[4];
    #pragma unroll
    for (int i = 0; i < 4; i++)
        r[i] = *(const float4*)&base[(size_t)i*HID + lane*4];

    float p[32];
    #pragma unroll
    for (int hh = 0; hh < NH; hh++) {
        float4 u4 = us4[hh][lane];
        #pragma unroll
        for (int i = 0; i < 4; i++)
            p[hh*4 + i] = r[i].x*u4.x + r[i].y*u4.y + r[i].z*u4.z + r[i].w*u4.w;
    }
    #pragma unroll
    for (int off = 16; off; off >>= 1) {
        bool up = (lane & off) != 0;
        #pragma unroll
        for (int k = 0; k < off; k++) {
            float a_ = p[k], b_ = p[k + off];
            float send = up ? a_ : b_;
            float keep = up ? b_ : a_;
            p[k] = keep + __shfl_xor_sync(FULL, send, off);
        }
    }
    float ev = __expf(0.25f*p[0]);          // lane l owns dot l (hh = l>>2, i = l&3)

    float4 acc[NH]; float eh[NH];
    #pragma unroll
    for (int hh = 0; hh < NH; hh++) {
        acc[hh] = make_float4(0.f,0.f,0.f,0.f); eh[hh] = 0.f;
        #pragma unroll
        for (int i = 0; i < 4; i++) {
            float e = __shfl_sync(FULL, ev, hh*4 + i);
            eh[hh] += e;
            acc[hh].x += e*r[i].x; acc[hh].y += e*r[i].y;
            acc[hh].z += e*r[i].z; acc[hh].w += e*r[i].w;
        }
    }
    // two-stage block reduce: warps 0-3 store; warps 4-7 add in; then 4-way sum
    __shared__ float4 smw[4][NH][32];                // 16KB
    __shared__ float  ses[8][NH];                    // 256B
    if (warp < 4) {
        #pragma unroll
        for (int hh = 0; hh < NH; hh++) smw[warp][hh][lane] = acc[hh];
    }
    if (lane == 0) {
        #pragma unroll
        for (int hh = 0; hh < NH; hh++) ses[warp][hh] = eh[hh];
    }
    __syncthreads();
    if (warp >= 4) {
        int w2 = warp - 4;
        #pragma unroll
        for (int hh = 0; hh < NH; hh++) {
            float4 v = smw[w2][hh][lane];
            v.x += acc[hh].x; v.y += acc[hh].y; v.z += acc[hh].z; v.w += acc[hh].w;
            smw[w2][hh][lane] = v;
        }
    }
    __syncthreads();
    int hh2 = tid >> 5;
    float4 rs = smw[0][hh2][lane];
    #pragma unroll
    for (int s = 1; s < 4; s++) {
        float4 v = smw[s][hh2][lane];
        rs.x += v.x; rs.y += v.y; rs.z += v.z; rs.w += v.w;
    }
    float* dst = &g_w[(b*NH + hh2)*HID + lane*4];
    atomicAdd(dst+0, rs.x); atomicAdd(dst+1, rs.y);
    atomicAdd(dst+2, rs.z); atomicAdd(dst+3, rs.w);
    if (tid < NH) {
        float s = 0.f;
        #pragma unroll
        for (int w2 = 0; w2 < 8; w2++) s += ses[w2][tid];
        atomicAdd(&g_sum[b*NH + tid], s);
    }
}

// ==== role DE: normalize w; y = w@W_v; mh = y@W_mhc; y2 = mh.hn; a/bv  (32 blocks/batch) ====
__device__ void roleDE(const float* __restrict__ h, const float* __restrict__ Wkv,
                       const float* __restrict__ Wmhc, const float* __restrict__ Wlin,
                       int b, int blk) {
    int tid = threadIdx.x;
    int t = tid & 127, k = tid >> 7;                 // k: 0..1
    __shared__ float ws[NH*HID], ys[HID], ms[HID], part[2][HID];
    __shared__ float ssum[NH], w01[2];
    if (tid < NH) ssum[tid] = g_sum[b*NH + tid];
    if (tid < 2)  w01[tid]  = Wlin[tid];
    __syncthreads();
    #pragma unroll
    for (int it = 0; it < 4; it++) {
        int i = tid + it*256;
        ws[i] = g_w[b*NH*HID + i] / ssum[i >> 7];
    }
    __syncthreads();
    int hh = t >> 4;
    float y = 0.f;
    #pragma unroll
    for (int jj = k*64; jj < k*64 + 64; jj++) y += ws[hh*HID + jj]*Wkv[jj*256 + HID + t];
    part[k][t] = y;
    __syncthreads();
    if (tid < HID) ys[tid] = part[0][tid] + part[1][tid];
    __syncthreads();
    float m = 0.f;
    #pragma unroll
    for (int c = k*64; c < k*64 + 64; c++) m += ys[c]*Wmhc[c*HID + t];
    part[k][t] = m;
    __syncthreads();
    if (tid < HID) ms[tid] = part[0][tid] + part[1][tid];
    __syncthreads();

    int warp = tid >> 5, lane = tid & 31;
    float4 m4 = ((float4*)ms)[lane];
    int row0 = blk*128 + warp*16;
    const float* base = &h[((size_t)b*SROW + row0)*HID];
    float out = 0.f;
    #pragma unroll
    for (int i = 0; i < 16; i++) {
        float4 r = *(const float4*)&base[(size_t)i*HID + lane*4];
        float d = r.x*m4.x + r.y*m4.y + r.z*m4.z + r.w*m4.w;
        d = wsum(d);
        if (lane == i) out = d;
    }
    if (lane < 16) {
        g_a [b*NSEQ + row0 + lane] = out*w01[0];
        g_bv[b*NSEQ + row0 + lane] = out*w01[1];
    }
}

// ==== role F: out[b, i*N + j] = a[b,j] + bv[b,i]  (4 rows/block, 1024 blocks/batch, 256 thr) ====
__device__ void roleF(float* __restrict__ out, int b, int blk) {
    int t = threadIdx.x;
    float4 a4[4];
    #pragma unroll
    for (int k = 0; k < 4; k++)
        a4[k] = ((const float4*)&g_a[b*NSEQ])[t + 256*k];
    const float* bv = &g_bv[b*NSEQ];
    int i0 = blk*4;
    float4* ob = (float4*)&out[((size_t)b*NSEQ + i0)*NSEQ];
    #pragma unroll
    for (int r = 0; r < 4; r++) {
        float bi = bv[i0 + r];
        #pragma unroll
        for (int k = 0; k < 4; k++) {
            float4 o4 = make_float4(a4[k].x+bi, a4[k].y+bi, a4[k].z+bi, a4[k].w+bi);
            __stwt(&ob[(size_t)r*(NSEQ/4) + t + 256*k], o4);
        }
    }
}

// ==== fused dispatcher: chain roles first, F blocks after; one wave per heavy launch ====
__global__ void __launch_bounds__(256)
kFuse(float* __restrict__ out, const float* __restrict__ h,
      const float* __restrict__ Wkv, const float* __restrict__ Wmhc,
      const float* __restrict__ Wlin,
      int nBC, int bcB0, int nDE, int deB0, int fB) {
    int bx = blockIdx.x;
    if (bx < nBC)            { roleBC(h, bcB0 + bx/128, bx % 128); return; }
    bx -= nBC;
    if (bx < nDE)            { roleDE(h, Wkv, Wmhc, Wlin, deB0 + bx/32, bx % 32); return; }
    bx -= nDE;
    roleF(out, fB + bx/1024, bx % 1024);
}

extern "C" void kernel_launch(void* const* d_in, const int* in_sizes, int n_in,
                              void* d_out, int out_size) {
    const float* h    = (const float*)d_in[0];
    const float* Wq   = (const float*)d_in[1];
    const float* Wkv  = (const float*)d_in[2];
    const float* Wmhc = (const float*)d_in[3];
    const float* Wlin = (const float*)d_in[4];
    float* out = (float*)d_out;

    // single-stream software pipeline; every producer 1+ launches ahead of its consumer
    kA<<<BP, 512>>>(h, Wq, Wkv);
    kFuse<<< 128, 256>>>(out, h, Wkv, Wmhc, Wlin, 128, 0,  0, 0, 0);  // BC(0)
    kFuse<<< 160, 256>>>(out, h, Wkv, Wmhc, Wlin, 128, 1, 32, 0, 0);  // BC(1) | DE(0)
    kFuse<<<1184, 256>>>(out, h, Wkv, Wmhc, Wlin, 128, 2, 32, 1, 0);  // BC(2) | DE(1) | F(0)
    kFuse<<<1184, 256>>>(out, h, Wkv, Wmhc, Wlin, 128, 3, 32, 2, 1);  // BC(3) | DE(2) | F(1)
    kFuse<<<1056, 256>>>(out, h, Wkv, Wmhc, Wlin,   0, 0, 32, 3, 2);  //         DE(3) | F(2)
    kFuse<<<1024, 256>>>(out, h, Wkv, Wmhc, Wlin,   0, 0,  0, 0, 3);  //                 F(3)
}

// round 12
// speedup vs baseline: 1.6049x; 1.2341x over previous
#include <cuda_runtime.h>

#define HID  128
#define NH   8
#define NSEQ 4096
#define BP   4
#define SROW 4097   // h has 4097 rows per batch; last row is hg
#define FULL 0xffffffffu

__device__ float g_u[BP*NH*HID];
__device__ float g_w[BP*NH*HID];     // UNNORMALIZED sum of e_n * hn
__device__ float g_sum[BP*NH];       // sum of e_n
__device__ float g_a[BP*NSEQ];
__device__ float g_bv[BP*NSEQ];

__device__ __forceinline__ float wsum(float v) {
    #pragma unroll
    for (int o = 16; o; o >>= 1) v += __shfl_xor_sync(FULL, v, o);
    return v;
}

// 32-dot warp transpose-reduce: lane l ends holding full dot l. 31 shfls.
__device__ __forceinline__ float treduce32(float* p, int lane) {
    #pragma unroll
    for (int off = 16; off; off >>= 1) {
        bool up = (lane & off) != 0;
        #pragma unroll
        for (int k = 0; k < off; k++) {
            float a_ = p[k], b_ = p[k + off];
            float send = up ? a_ : b_;
            float keep = up ? b_ : a_;
            p[k] = keep + __shfl_xor_sync(FULL, send, off);
        }
    }
    return p[0];
}

// ---------------- kA: q = hg@W_q ; u_h = W_k_head@q_h ; zero accumulators ----------------
__global__ void kA(const float* __restrict__ h, const float* __restrict__ Wq,
                   const float* __restrict__ Wkv) {
    int b = blockIdx.x, tid = threadIdx.x;           // 512 threads
    g_w[b*NH*HID + tid]       = 0.f;
    g_w[b*NH*HID + 512 + tid] = 0.f;
    if (tid < NH) g_sum[b*NH + tid] = 0.f;

    int t = tid & 127, k = tid >> 7;
    __shared__ float hg[HID], qp[4][HID], qs[HID];
    if (tid < HID) hg[tid] = h[((size_t)b*SROW + NSEQ)*HID + tid];
    __syncthreads();
    float q = 0.f;
    #pragma unroll
    for (int d = k*32; d < k*32 + 32; d++) q += hg[d]*Wq[d*HID + t];
    qp[k][t] = q;
    __syncthreads();
    if (tid < HID) qs[tid] = qp[0][tid] + qp[1][tid] + qp[2][tid] + qp[3][tid];
    __syncthreads();
    #pragma unroll
    for (int it = 0; it < 2; it++) {
        int idx = tid + it*512;
        int hh = idx >> 7, tt = idx & 127;
        float u = 0.f;
        #pragma unroll
        for (int d = 0; d < 16; d++) u += Wkv[tt*256 + hh*16 + d]*qs[hh*16 + d];
        g_u[(b*NH + hh)*HID + tt] = u;
    }
}

// ==== kBC: scores -> exp -> accumulate w, esum ====
// grid (NSEQ/64, BP) x 256 threads; 8 warps x 8 rows (MLP=8, two 32-dot reduces).
__global__ void kBC(const float* __restrict__ h) {
    int b = blockIdx.y, tid = threadIdx.x;
    int warp = tid >> 5, lane = tid & 31;
    __shared__ float4 us4[NH][32];
    ((float4*)us4)[tid] = ((const float4*)&g_u[b*NH*HID])[tid];
    __syncthreads();

    int row0 = blockIdx.x*64 + warp*8;
    const float* base = &h[((size_t)b*SROW + row0)*HID];
    float4 r[8];
    #pragma unroll
    for (int i = 0; i < 8; i++)
        r[i] = *(const float4*)&base[(size_t)i*HID + lane*4];

    float p[32];
    // group 0: rows 0..3
    #pragma unroll
    for (int hh = 0; hh < NH; hh++) {
        float4 u4 = us4[hh][lane];
        #pragma unroll
        for (int i = 0; i < 4; i++)
            p[hh*4 + i] = r[i].x*u4.x + r[i].y*u4.y + r[i].z*u4.z + r[i].w*u4.w;
    }
    float ev0 = __expf(0.25f*treduce32(p, lane));
    // group 1: rows 4..7
    #pragma unroll
    for (int hh = 0; hh < NH; hh++) {
        float4 u4 = us4[hh][lane];
        #pragma unroll
        for (int i = 0; i < 4; i++)
            p[hh*4 + i] = r[i+4].x*u4.x + r[i+4].y*u4.y + r[i+4].z*u4.z + r[i+4].w*u4.w;
    }
    float ev1 = __expf(0.25f*treduce32(p, lane));

    float4 acc[NH]; float eh[NH];
    #pragma unroll
    for (int hh = 0; hh < NH; hh++) {
        acc[hh] = make_float4(0.f,0.f,0.f,0.f); eh[hh] = 0.f;
        #pragma unroll
        for (int i = 0; i < 4; i++) {
            float e0 = __shfl_sync(FULL, ev0, hh*4 + i);
            float e1 = __shfl_sync(FULL, ev1, hh*4 + i);
            eh[hh] += e0 + e1;
            acc[hh].x += e0*r[i].x + e1*r[i+4].x;
            acc[hh].y += e0*r[i].y + e1*r[i+4].y;
            acc[hh].z += e0*r[i].z + e1*r[i+4].z;
            acc[hh].w += e0*r[i].w + e1*r[i+4].w;
        }
    }
    __shared__ float4 smw[8][NH][32];       // 32KB
    __shared__ float  ses[8][NH];
    #pragma unroll
    for (int hh = 0; hh < NH; hh++) smw[warp][hh][lane] = acc[hh];
    if (lane == 0) {
        #pragma unroll
        for (int hh = 0; hh < NH; hh++) ses[warp][hh] = eh[hh];
    }
    __syncthreads();
    int hh2 = tid >> 5;
    float4 rs = smw[0][hh2][lane];
    #pragma unroll
    for (int s = 1; s < 8; s++) {
        float4 v = smw[s][hh2][lane];
        rs.x += v.x; rs.y += v.y; rs.z += v.z; rs.w += v.w;
    }
    float* dst = &g_w[(b*NH + hh2)*HID + lane*4];
    atomicAdd(dst+0, rs.x); atomicAdd(dst+1, rs.y);
    atomicAdd(dst+2, rs.z); atomicAdd(dst+3, rs.w);
    if (tid < NH) {
        float s = 0.f;
        #pragma unroll
        for (int w2 = 0; w2 < 8; w2++) s += ses[w2][tid];
        atomicAdd(&g_sum[b*NH + tid], s);
    }
}

// ==== kDE: normalize w; y = w@W_v; mh = y@W_mhc; y2 = mh.hn; a/bv ====
// grid (NSEQ/128, BP) x 256 threads (8 warps x 16 rows).
__global__ void kDE(const float* __restrict__ h, const float* __restrict__ Wkv,
                    const float* __restrict__ Wmhc, const float* __restrict__ Wlin) {
    int b = blockIdx.y, tid = threadIdx.x;
    int t = tid & 127, k = tid >> 7;                 // k: 0..1
    __shared__ float ws[NH*HID], ys[HID], ms[HID], part[2][HID];
    __shared__ float ssum[NH], w01[2];
    if (tid < NH) ssum[tid] = g_sum[b*NH + tid];
    if (tid < 2)  w01[tid]  = Wlin[tid];
    __syncthreads();
    #pragma unroll
    for (int it = 0; it < 4; it++) {
        int i = tid + it*256;
        ws[i] = g_w[b*NH*HID + i] / ssum[i >> 7];
    }
    __syncthreads();
    int hh = t >> 4;
    float y = 0.f;
    #pragma unroll
    for (int jj = k*64; jj < k*64 + 64; jj++) y += ws[hh*HID + jj]*Wkv[jj*256 + HID + t];
    part[k][t] = y;
    __syncthreads();
    if (tid < HID) ys[tid] = part[0][tid] + part[1][tid];
    __syncthreads();
    float m = 0.f;
    #pragma unroll
    for (int c = k*64; c < k*64 + 64; c++) m += ys[c]*Wmhc[c*HID + t];
    part[k][t] = m;
    __syncthreads();
    if (tid < HID) ms[tid] = part[0][tid] + part[1][tid];
    __syncthreads();

    int warp = tid >> 5, lane = tid & 31;
    float4 m4 = ((float4*)ms)[lane];
    int row0 = blockIdx.x*128 + warp*16;
    const float* base = &h[((size_t)b*SROW + row0)*HID];
    float out = 0.f;
    #pragma unroll
    for (int i = 0; i < 16; i++) {
        float4 r = *(const float4*)&base[(size_t)i*HID + lane*4];
        float d = r.x*m4.x + r.y*m4.y + r.z*m4.z + r.w*m4.w;
        d = wsum(d);
        if (lane == i) out = d;
    }
    if (lane < 16) {
        g_a [b*NSEQ + row0 + lane] = out*w01[0];
        g_bv[b*NSEQ + row0 + lane] = out*w01[1];
    }
}

// ==== kF: out[b, i*N + j] = a[b,j] + bv[b,i]  (268MB stream) ====
#define ROWS_F 16
__global__ void kF(float* __restrict__ out) {
    int b = blockIdx.y, t = threadIdx.x;                     // 1024 threads
    int i0 = blockIdx.x*ROWS_F;
    float4 a4 = ((const float4*)&g_a[b*NSEQ])[t];
    const float* bv = &g_bv[b*NSEQ];
    float4* ob = (float4*)&out[((size_t)b*NSEQ + i0)*NSEQ];
    #pragma unroll
    for (int r = 0; r < ROWS_F; r++) {
        float bi = bv[i0 + r];
        float4 o4 = make_float4(a4.x+bi, a4.y+bi, a4.z+bi, a4.w+bi);
        __stwt(&ob[(size_t)r*(NSEQ/4) + t], o4);
    }
}

extern "C" void kernel_launch(void* const* d_in, const int* in_sizes, int n_in,
                              void* d_out, int out_size) {
    const float* h    = (const float*)d_in[0];
    const float* Wq   = (const float*)d_in[1];
    const float* Wkv  = (const float*)d_in[2];
    const float* Wmhc = (const float*)d_in[3];
    const float* Wlin = (const float*)d_in[4];
    float* out = (float*)d_out;

    kA  <<<BP, 512>>>(h, Wq, Wkv);
    kBC <<<dim3(NSEQ/64, BP), 256>>>(h);
    kDE <<<dim3(NSEQ/128, BP), 256>>>(h, Wkv, Wmhc, Wlin);
    kF  <<<dim3(NSEQ/ROWS_F, BP), 1024>>>(out);
}